// round 1
// baseline (speedup 1.0000x reference)
#include <cuda_runtime.h>
#include <math.h>

#define DIM   512
#define HEADS 8
#define DQ    64
#define SEQ   4096
#define BATCH 2
#define NTOK  (BATCH * SEQ)   // 8192

// Scratch (allocation-free rule: __device__ globals)
__device__ float g_q [NTOK * DIM];
__device__ float g_k [NTOK * DIM];
__device__ float g_v [NTOK * DIM];
__device__ float g_ao[NTOK * DIM];

// ---------------------------------------------------------------------------
// GEMM with bias: C[n,m] = sum_k X[n,k] * W[m,k] + bias[m]   (K = DIM = 512)
// 64x64 tile, 256 threads, 4x4 microtile, K-step 32.
// ---------------------------------------------------------------------------
__global__ __launch_bounds__(256) void gemm_bias_kernel(
    const float* __restrict__ X, const float* __restrict__ W,
    const float* __restrict__ bias, float* __restrict__ C)
{
    __shared__ float Xs[64][33];
    __shared__ float Ws[64][33];

    const int tid = threadIdx.x;
    const int tx = tid & 15;
    const int ty = tid >> 4;
    const int n0 = blockIdx.x * 64;
    const int m0 = blockIdx.y * 64;

    float acc[4][4] = {};

    for (int k0 = 0; k0 < DIM; k0 += 32) {
        #pragma unroll
        for (int r = 0; r < 2; r++) {
            int e   = tid + 256 * r;
            int row = e >> 3;
            int c4  = (e & 7) * 4;
            float4 xa = *(const float4*)&X[(size_t)(n0 + row) * DIM + k0 + c4];
            Xs[row][c4 + 0] = xa.x; Xs[row][c4 + 1] = xa.y;
            Xs[row][c4 + 2] = xa.z; Xs[row][c4 + 3] = xa.w;
            float4 wa = *(const float4*)&W[(size_t)(m0 + row) * DIM + k0 + c4];
            Ws[row][c4 + 0] = wa.x; Ws[row][c4 + 1] = wa.y;
            Ws[row][c4 + 2] = wa.z; Ws[row][c4 + 3] = wa.w;
        }
        __syncthreads();

        #pragma unroll
        for (int kk = 0; kk < 32; kk++) {
            float a[4], b[4];
            #pragma unroll
            for (int i = 0; i < 4; i++) a[i] = Xs[ty * 4 + i][kk];
            #pragma unroll
            for (int j = 0; j < 4; j++) b[j] = Ws[tx * 4 + j][kk];
            #pragma unroll
            for (int i = 0; i < 4; i++)
                #pragma unroll
                for (int j = 0; j < 4; j++)
                    acc[i][j] = fmaf(a[i], b[j], acc[i][j]);
        }
        __syncthreads();
    }

    #pragma unroll
    for (int j = 0; j < 4; j++) {
        float bj = bias[m0 + tx * 4 + j];
        #pragma unroll
        for (int i = 0; i < 4; i++)
            C[(size_t)(n0 + ty * 4 + i) * DIM + m0 + tx * 4 + j] = acc[i][j] + bj;
    }
}

// ---------------------------------------------------------------------------
// Flash attention (fp32, online softmax).
// Grid: (SEQ/64, HEADS, BATCH). Block 256 threads (16x16), 4x4 microtiles.
// Q tile 64 rows x 64 dq; iterate 64-key tiles over the full sequence.
// ---------------------------------------------------------------------------
#define SM_Q  0
#define SM_K  (64 * 65)
#define SM_V  (2 * 64 * 65)
#define SM_P  (3 * 64 * 65)
#define ATTN_SMEM_BYTES (4 * 64 * 65 * sizeof(float))

__global__ __launch_bounds__(256) void attn_kernel(
    const float* __restrict__ Q, const float* __restrict__ K,
    const float* __restrict__ V, float* __restrict__ O)
{
    extern __shared__ float sm[];
    float (*Qs)[65] = (float(*)[65])(sm + SM_Q);
    float (*Ks)[65] = (float(*)[65])(sm + SM_K);
    float (*Vs)[65] = (float(*)[65])(sm + SM_V);
    float (*Ps)[65] = (float(*)[65])(sm + SM_P);

    const int tid = threadIdx.x;
    const int tx  = tid & 15;
    const int ty  = tid >> 4;
    const int q0  = blockIdx.x * 64;
    const int h   = blockIdx.y;
    const int b   = blockIdx.z;
    const size_t base = (size_t)b * SEQ * DIM + (size_t)h * DQ;
    const float scale = 0.125f;  // 1/sqrt(64)

    // Load Q tile (64 x 64)
    #pragma unroll
    for (int r = 0; r < 4; r++) {
        int e   = tid + 256 * r;
        int row = e >> 4;
        int c4  = (e & 15) * 4;
        float4 qa = *(const float4*)&Q[base + (size_t)(q0 + row) * DIM + c4];
        Qs[row][c4 + 0] = qa.x; Qs[row][c4 + 1] = qa.y;
        Qs[row][c4 + 2] = qa.z; Qs[row][c4 + 3] = qa.w;
    }

    float m_i[4], l_i[4], oacc[4][4] = {};
    #pragma unroll
    for (int i = 0; i < 4; i++) { m_i[i] = -1e30f; l_i[i] = 0.0f; }

    for (int k0 = 0; k0 < SEQ; k0 += 64) {
        // Load K and V tiles (64 x 64 each)
        #pragma unroll
        for (int r = 0; r < 4; r++) {
            int e   = tid + 256 * r;
            int row = e >> 4;
            int c4  = (e & 15) * 4;
            float4 ka = *(const float4*)&K[base + (size_t)(k0 + row) * DIM + c4];
            Ks[row][c4 + 0] = ka.x; Ks[row][c4 + 1] = ka.y;
            Ks[row][c4 + 2] = ka.z; Ks[row][c4 + 3] = ka.w;
            float4 va = *(const float4*)&V[base + (size_t)(k0 + row) * DIM + c4];
            Vs[row][c4 + 0] = va.x; Vs[row][c4 + 1] = va.y;
            Vs[row][c4 + 2] = va.z; Vs[row][c4 + 3] = va.w;
        }
        __syncthreads();

        // S = Q @ K^T  (thread owns rows ty*4+i, key-cols tx*4+j)
        float s[4][4] = {};
        #pragma unroll
        for (int kk = 0; kk < 64; kk++) {
            float qv[4], kv[4];
            #pragma unroll
            for (int i = 0; i < 4; i++) qv[i] = Qs[ty * 4 + i][kk];
            #pragma unroll
            for (int j = 0; j < 4; j++) kv[j] = Ks[tx * 4 + j][kk];
            #pragma unroll
            for (int i = 0; i < 4; i++)
                #pragma unroll
                for (int j = 0; j < 4; j++)
                    s[i][j] = fmaf(qv[i], kv[j], s[i][j]);
        }

        // Online softmax per row (reduce across the 16 tx lanes; width-16 shfl)
        #pragma unroll
        for (int i = 0; i < 4; i++) {
            float tm = -1e30f;
            #pragma unroll
            for (int j = 0; j < 4; j++) {
                s[i][j] *= scale;
                tm = fmaxf(tm, s[i][j]);
            }
            #pragma unroll
            for (int off = 8; off >= 1; off >>= 1)
                tm = fmaxf(tm, __shfl_xor_sync(0xffffffffu, tm, off, 16));

            float mnew = fmaxf(m_i[i], tm);
            float rs = 0.0f;
            #pragma unroll
            for (int j = 0; j < 4; j++) {
                s[i][j] = __expf(s[i][j] - mnew);
                rs += s[i][j];
            }
            #pragma unroll
            for (int off = 8; off >= 1; off >>= 1)
                rs += __shfl_xor_sync(0xffffffffu, rs, off, 16);

            float alpha = __expf(m_i[i] - mnew);
            l_i[i] = l_i[i] * alpha + rs;
            m_i[i] = mnew;
            #pragma unroll
            for (int j = 0; j < 4; j++) {
                oacc[i][j] *= alpha;
                Ps[ty * 4 + i][tx * 4 + j] = s[i][j];
            }
        }
        __syncthreads();

        // O += P @ V  (thread owns rows ty*4+i, dq-cols tx*4+j)
        #pragma unroll
        for (int kk = 0; kk < 64; kk++) {
            float pv[4], vv[4];
            #pragma unroll
            for (int i = 0; i < 4; i++) pv[i] = Ps[ty * 4 + i][kk];
            #pragma unroll
            for (int j = 0; j < 4; j++) vv[j] = Vs[kk][tx * 4 + j];
            #pragma unroll
            for (int i = 0; i < 4; i++)
                #pragma unroll
                for (int j = 0; j < 4; j++)
                    oacc[i][j] = fmaf(pv[i], vv[j], oacc[i][j]);
        }
        __syncthreads();
    }

    #pragma unroll
    for (int i = 0; i < 4; i++) {
        float inv = 1.0f / l_i[i];
        #pragma unroll
        for (int j = 0; j < 4; j++)
            O[base + (size_t)(q0 + ty * 4 + i) * DIM + tx * 4 + j] = oacc[i][j] * inv;
    }
}

// ---------------------------------------------------------------------------
extern "C" void kernel_launch(void* const* d_in, const int* in_sizes, int n_in,
                              void* d_out, int out_size)
{
    const float* x  = (const float*)d_in[0];
    const float* Wq = (const float*)d_in[1];
    const float* bq = (const float*)d_in[2];
    const float* Wk = (const float*)d_in[3];
    const float* bk = (const float*)d_in[4];
    const float* Wv = (const float*)d_in[5];
    const float* bv = (const float*)d_in[6];
    const float* Wo = (const float*)d_in[7];
    const float* bo = (const float*)d_in[8];
    float* out = (float*)d_out;

    float *qp, *kp, *vp, *aop;
    cudaGetSymbolAddress((void**)&qp,  g_q);
    cudaGetSymbolAddress((void**)&kp,  g_k);
    cudaGetSymbolAddress((void**)&vp,  g_v);
    cudaGetSymbolAddress((void**)&aop, g_ao);

    dim3 gridP(NTOK / 64, DIM / 64);  // 128 x 8

    gemm_bias_kernel<<<gridP, 256>>>(x, Wq, bq, qp);
    gemm_bias_kernel<<<gridP, 256>>>(x, Wk, bk, kp);
    gemm_bias_kernel<<<gridP, 256>>>(x, Wv, bv, vp);

    cudaFuncSetAttribute(attn_kernel,
                         cudaFuncAttributeMaxDynamicSharedMemorySize,
                         (int)ATTN_SMEM_BYTES);
    dim3 gridA(SEQ / 64, HEADS, BATCH);  // 64 x 8 x 2
    attn_kernel<<<gridA, 256, ATTN_SMEM_BYTES>>>(qp, kp, vp, aop);

    gemm_bias_kernel<<<gridP, 256>>>(aop, Wo, bo, out);
}

// round 4
// speedup vs baseline: 3.3454x; 3.3454x over previous
#include <cuda_runtime.h>
#include <math.h>
#include <stdint.h>

#define DIM   512
#define HEADS 8
#define DQ    64
#define SEQ   4096
#define BATCH 2
#define NTOK  (BATCH * SEQ)   // 8192

// Scratch (allocation-free rule: __device__ globals)
__device__ float g_q [NTOK * DIM];
__device__ float g_k [NTOK * DIM];
__device__ float g_vt[NTOK * DIM];   // V stored transposed: [b*512 + m][4096]
__device__ float g_ao[NTOK * DIM];

// ---------------------------------------------------------------------------
// tf32 helpers
// ---------------------------------------------------------------------------
__device__ __forceinline__ uint32_t f2tf32(float f) {
    uint32_t u; asm("cvt.rna.tf32.f32 %0, %1;" : "=r"(u) : "f"(f)); return u;
}
__device__ __forceinline__ float f2tf32f(float f) { return __uint_as_float(f2tf32(f)); }

__device__ __forceinline__ void sts_tf4(float* d, float4 v) {
    d[0] = f2tf32f(v.x); d[1] = f2tf32f(v.y);
    d[2] = f2tf32f(v.z); d[3] = f2tf32f(v.w);
}

__device__ __forceinline__ void ldsm_x4(uint32_t r[4], const float* p) {
    uint32_t a = (uint32_t)__cvta_generic_to_shared(p);
    asm volatile("ldmatrix.sync.aligned.m8n8.x4.shared.b16 {%0,%1,%2,%3}, [%4];"
                 : "=r"(r[0]), "=r"(r[1]), "=r"(r[2]), "=r"(r[3])
                 : "r"(a) : "memory");
}

__device__ __forceinline__ void mma_tf32(float c[4], const uint32_t a[4],
                                         uint32_t b0, uint32_t b1) {
    asm volatile("mma.sync.aligned.m16n8k8.row.col.f32.tf32.tf32.f32 "
                 "{%0,%1,%2,%3}, {%4,%5,%6,%7}, {%8,%9}, {%0,%1,%2,%3};"
                 : "+f"(c[0]), "+f"(c[1]), "+f"(c[2]), "+f"(c[3])
                 : "r"(a[0]), "r"(a[1]), "r"(a[2]), "r"(a[3]), "r"(b0), "r"(b1));
}

// ---------------------------------------------------------------------------
// Tensor-core GEMM: C[n,m] = sum_k X[n,k]*W[m,k] + bias[m]   (K = 512)
// CTA: 128 tokens x 64 cols.  8 warps, each 16 rows x 64 cols.
// transposed!=0: write C^T into [(b*512 + m)][4096] layout (for V).
// ---------------------------------------------------------------------------
#define GP 36   // shared pitch (floats): 144B, bank stride 4 -> ldsm conflict-free

__global__ __launch_bounds__(256) void gemm_tc(
    const float* __restrict__ X, const float* __restrict__ W,
    const float* __restrict__ bias, float* __restrict__ C, int transposed)
{
    __shared__ float Xs[128 * GP];
    __shared__ float Ws[64 * GP];

    const int tid = threadIdx.x;
    const int L   = tid & 31;
    const int wid = tid >> 5;
    const int n0  = blockIdx.x * 128;
    const int m0  = blockIdx.y * 64;

    float c[8][4] = {};

    const int arow = wid * 16 + ((L >> 3) & 1) * 8 + (L & 7);
    const int acol = (L >> 4) * 4;
    const int brow = (L >> 4) * 8 + (L & 7);
    const int bcol = ((L >> 3) & 1) * 4;

    for (int k0 = 0; k0 < DIM; k0 += 32) {
        #pragma unroll
        for (int r = 0; r < 4; r++) {            // X tile 128x32
            int e = tid + 256 * r;
            int row = e >> 3, c4 = (e & 7) * 4;
            float4 v = *(const float4*)&X[(size_t)(n0 + row) * DIM + k0 + c4];
            sts_tf4(&Xs[row * GP + c4], v);
        }
        #pragma unroll
        for (int r = 0; r < 2; r++) {            // W tile 64x32
            int e = tid + 256 * r;
            int row = e >> 3, c4 = (e & 7) * 4;
            float4 v = *(const float4*)&W[(size_t)(m0 + row) * DIM + k0 + c4];
            sts_tf4(&Ws[row * GP + c4], v);
        }
        __syncthreads();

        #pragma unroll
        for (int ks = 0; ks < 4; ks++) {
            uint32_t a[4];
            ldsm_x4(a, &Xs[arow * GP + ks * 8 + acol]);
            #pragma unroll
            for (int jp = 0; jp < 4; jp++) {
                uint32_t b[4];
                ldsm_x4(b, &Ws[(jp * 16 + brow) * GP + ks * 8 + bcol]);
                mma_tf32(c[jp * 2 + 0], a, b[0], b[1]);
                mma_tf32(c[jp * 2 + 1], a, b[2], b[3]);
            }
        }
        __syncthreads();
    }

    const int rlo  = n0 + wid * 16 + (L >> 2);
    const int colb = 2 * (L & 3);
    if (!transposed) {
        #pragma unroll
        for (int j = 0; j < 8; j++) {
            int col = m0 + j * 8 + colb;
            float b0 = bias[col], b1 = bias[col + 1];
            *(float2*)&C[(size_t)rlo * DIM + col] =
                make_float2(c[j][0] + b0, c[j][1] + b1);
            *(float2*)&C[(size_t)(rlo + 8) * DIM + col] =
                make_float2(c[j][2] + b0, c[j][3] + b1);
        }
    } else {
        int b_lo = rlo >> 12, t_lo = rlo & 4095;
        int rhi = rlo + 8;
        int b_hi = rhi >> 12, t_hi = rhi & 4095;
        #pragma unroll
        for (int j = 0; j < 8; j++) {
            int m = m0 + j * 8 + colb;
            float bb0 = bias[m], bb1 = bias[m + 1];
            C[(size_t)(b_lo * DIM + m)     * SEQ + t_lo] = c[j][0] + bb0;
            C[(size_t)(b_lo * DIM + m + 1) * SEQ + t_lo] = c[j][1] + bb1;
            C[(size_t)(b_hi * DIM + m)     * SEQ + t_hi] = c[j][2] + bb0;
            C[(size_t)(b_hi * DIM + m + 1) * SEQ + t_hi] = c[j][3] + bb1;
        }
    }
}

// ---------------------------------------------------------------------------
// Tensor-core flash attention.
// Grid (SEQ/128, HEADS, BATCH); block 256 (8 warps x 16 q-rows).
// Q frags preloaded to registers; P reuses Q's smem (warp-private rows).
// ---------------------------------------------------------------------------
#define AP 68   // shared pitch (floats): 272B, bank stride 4 -> ldsm conflict-free
#define ATTN_SMEM ((128 + 64 + 64) * AP * sizeof(float))   // 69632 B

__global__ __launch_bounds__(256, 2) void attn_tc(
    const float* __restrict__ Q, const float* __restrict__ K,
    const float* __restrict__ Vt, float* __restrict__ O)
{
    extern __shared__ float sm[];
    float* QPs = sm;                 // 128 x 68 : Q tile, then P tile
    float* Ksm = sm + 128 * AP;      // 64 x 68
    float* Vsm = sm + 192 * AP;      // 64 x 68 : Vt tile [dq][key]

    const int tid = threadIdx.x;
    const int L   = tid & 31;
    const int wid = tid >> 5;
    const int q0  = blockIdx.x * 128;
    const int h   = blockIdx.y;
    const int b   = blockIdx.z;
    const size_t qk_base = (size_t)b * SEQ * DIM + (size_t)h * DQ;
    const size_t vt_base = (size_t)(b * DIM + h * DQ) * SEQ;

    // Load Q tile (scaled by 1/sqrt(dq), tf32-rounded)
    #pragma unroll
    for (int r = 0; r < 8; r++) {
        int e = tid + 256 * r;               // 2048 float4s
        int row = e >> 4, c4 = (e & 15) * 4;
        float4 v = *(const float4*)&Q[qk_base + (size_t)(q0 + row) * DIM + c4];
        v.x *= 0.125f; v.y *= 0.125f; v.z *= 0.125f; v.w *= 0.125f;
        sts_tf4(&QPs[row * AP + c4], v);
    }
    __syncthreads();

    const int arow = wid * 16 + ((L >> 3) & 1) * 8 + (L & 7);
    const int acol = (L >> 4) * 4;
    const int brow = (L >> 4) * 8 + (L & 7);
    const int bcol = ((L >> 3) & 1) * 4;

    uint32_t qf[8][4];
    #pragma unroll
    for (int ks = 0; ks < 8; ks++)
        ldsm_x4(qf[ks], &QPs[arow * AP + ks * 8 + acol]);

    float m_lo = -1e30f, m_hi = -1e30f, l_lo = 0.f, l_hi = 0.f;
    float o[8][4] = {};

    for (int k0 = 0; k0 < SEQ; k0 += 64) {
        // Load K tile [key][dk] and Vt tile [dq][key]
        #pragma unroll
        for (int r = 0; r < 4; r++) {
            int e = tid + 256 * r;           // 1024 float4s each
            int row = e >> 4, c4 = (e & 15) * 4;
            float4 kv = *(const float4*)&K[qk_base + (size_t)(k0 + row) * DIM + c4];
            sts_tf4(&Ksm[row * AP + c4], kv);
            float4 vv = *(const float4*)&Vt[vt_base + (size_t)row * SEQ + k0 + c4];
            sts_tf4(&Vsm[row * AP + c4], vv);
        }
        __syncthreads();

        // S = Q @ K^T  (16 rows x 64 keys per warp)
        float s[8][4] = {};
        #pragma unroll
        for (int ks = 0; ks < 8; ks++) {
            #pragma unroll
            for (int jp = 0; jp < 4; jp++) {
                uint32_t bf[4];
                ldsm_x4(bf, &Ksm[(jp * 16 + brow) * AP + ks * 8 + bcol]);
                mma_tf32(s[jp * 2 + 0], qf[ks], bf[0], bf[1]);
                mma_tf32(s[jp * 2 + 1], qf[ks], bf[2], bf[3]);
            }
        }

        // Online softmax (rows: lo = base + L/4, hi = +8)
        float mx_lo = -1e30f, mx_hi = -1e30f;
        #pragma unroll
        for (int j = 0; j < 8; j++) {
            mx_lo = fmaxf(mx_lo, fmaxf(s[j][0], s[j][1]));
            mx_hi = fmaxf(mx_hi, fmaxf(s[j][2], s[j][3]));
        }
        mx_lo = fmaxf(mx_lo, __shfl_xor_sync(0xffffffffu, mx_lo, 1));
        mx_lo = fmaxf(mx_lo, __shfl_xor_sync(0xffffffffu, mx_lo, 2));
        mx_hi = fmaxf(mx_hi, __shfl_xor_sync(0xffffffffu, mx_hi, 1));
        mx_hi = fmaxf(mx_hi, __shfl_xor_sync(0xffffffffu, mx_hi, 2));

        float mn_lo = fmaxf(m_lo, mx_lo), mn_hi = fmaxf(m_hi, mx_hi);
        float al = __expf(m_lo - mn_lo),  ah = __expf(m_hi - mn_hi);
        m_lo = mn_lo; m_hi = mn_hi;

        float sum_lo = 0.f, sum_hi = 0.f;
        #pragma unroll
        for (int j = 0; j < 8; j++) {
            s[j][0] = __expf(s[j][0] - mn_lo);
            s[j][1] = __expf(s[j][1] - mn_lo);
            s[j][2] = __expf(s[j][2] - mn_hi);
            s[j][3] = __expf(s[j][3] - mn_hi);
            sum_lo += s[j][0] + s[j][1];
            sum_hi += s[j][2] + s[j][3];
        }
        sum_lo += __shfl_xor_sync(0xffffffffu, sum_lo, 1);
        sum_lo += __shfl_xor_sync(0xffffffffu, sum_lo, 2);
        sum_hi += __shfl_xor_sync(0xffffffffu, sum_hi, 1);
        sum_hi += __shfl_xor_sync(0xffffffffu, sum_hi, 2);
        l_lo = l_lo * al + sum_lo;
        l_hi = l_hi * ah + sum_hi;

        #pragma unroll
        for (int j = 0; j < 8; j++) {
            o[j][0] *= al; o[j][1] *= al;
            o[j][2] *= ah; o[j][3] *= ah;
        }

        // Store P (tf32) into warp-private rows of QPs
        const int prow = wid * 16 + (L >> 2);
        #pragma unroll
        for (int j = 0; j < 8; j++) {
            int col = j * 8 + 2 * (L & 3);
            *(float2*)&QPs[prow * AP + col] =
                make_float2(f2tf32f(s[j][0]), f2tf32f(s[j][1]));
            *(float2*)&QPs[(prow + 8) * AP + col] =
                make_float2(f2tf32f(s[j][2]), f2tf32f(s[j][3]));
        }
        __syncwarp();

        // O += P @ V  (B frags from Vt tile: B[k=key][n=dq] = Vsm[dq][key])
        #pragma unroll
        for (int ks = 0; ks < 8; ks++) {
            uint32_t a[4];
            ldsm_x4(a, &QPs[arow * AP + ks * 8 + acol]);
            #pragma unroll
            for (int jp = 0; jp < 4; jp++) {
                uint32_t bf[4];
                ldsm_x4(bf, &Vsm[(jp * 16 + brow) * AP + ks * 8 + bcol]);
                mma_tf32(o[jp * 2 + 0], a, bf[0], bf[1]);
                mma_tf32(o[jp * 2 + 1], a, bf[2], bf[3]);
            }
        }
        __syncthreads();   // protect Ksm/Vsm before next tile load
    }

    // Epilogue
    float il = 1.f / l_lo, ih = 1.f / l_hi;
    const int row = q0 + wid * 16 + (L >> 2);
    #pragma unroll
    for (int j = 0; j < 8; j++) {
        int col = j * 8 + 2 * (L & 3);
        *(float2*)&O[qk_base + (size_t)row * DIM + col] =
            make_float2(o[j][0] * il, o[j][1] * il);
        *(float2*)&O[qk_base + (size_t)(row + 8) * DIM + col] =
            make_float2(o[j][2] * ih, o[j][3] * ih);
    }
}

// ---------------------------------------------------------------------------
extern "C" void kernel_launch(void* const* d_in, const int* in_sizes, int n_in,
                              void* d_out, int out_size)
{
    const float* x  = (const float*)d_in[0];
    const float* Wq = (const float*)d_in[1];
    const float* bq = (const float*)d_in[2];
    const float* Wk = (const float*)d_in[3];
    const float* bk = (const float*)d_in[4];
    const float* Wv = (const float*)d_in[5];
    const float* bv = (const float*)d_in[6];
    const float* Wo = (const float*)d_in[7];
    const float* bo = (const float*)d_in[8];
    float* out = (float*)d_out;

    float *qp, *kp, *vtp, *aop;
    cudaGetSymbolAddress((void**)&qp,  g_q);
    cudaGetSymbolAddress((void**)&kp,  g_k);
    cudaGetSymbolAddress((void**)&vtp, g_vt);
    cudaGetSymbolAddress((void**)&aop, g_ao);

    dim3 gridP(NTOK / 128, DIM / 64);   // 64 x 8

    gemm_tc<<<gridP, 256>>>(x, Wq, bq, qp, 0);
    gemm_tc<<<gridP, 256>>>(x, Wk, bk, kp, 0);
    gemm_tc<<<gridP, 256>>>(x, Wv, bv, vtp, 1);

    cudaFuncSetAttribute(attn_tc,
                         cudaFuncAttributeMaxDynamicSharedMemorySize,
                         (int)ATTN_SMEM);
    dim3 gridA(SEQ / 128, HEADS, BATCH);  // 32 x 8 x 2
    attn_tc<<<gridA, 256, ATTN_SMEM>>>(qp, kp, vtp, aop);

    gemm_tc<<<gridP, 256>>>(aop, Wo, bo, out, 0);
}